// round 1
// baseline (speedup 1.0000x reference)
#include <cuda_runtime.h>

#define RS2 0.7071067811865476f
#define TAU_V 0.05f

constexpr int SH = 33;
constexpr int SD = 33 * 33;          // 1089
constexpr int TILE_F = 32 * SD;      // 34848 floats
constexpr int ACC_F  = 32 * 512;     // 16384 floats
constexpr int NTHREADS = 256;

extern __shared__ float smem[];

// ---- one axis pass of length-N Haar DWT over a family of lines (in place) ----
template<int N>
__device__ __forceinline__ void dwt_pass(float* T, int tid, int sLine, int sA, int sB, int nA, int nB) {
    const int nl = nA * nB;
    for (int li = tid; li < nl; li += NTHREADS) {
        int a = li / nB, b = li - a * nB;
        float* p = T + a * sA + b * sB;
        float v[N];
#pragma unroll
        for (int k = 0; k < N; k++) v[k] = p[k * sLine];
#pragma unroll
        for (int i = 0; i < N / 2; i++) {
            p[i * sLine]         = (v[2*i] + v[2*i+1]) * RS2;
            p[(i + N/2) * sLine] = (v[2*i] - v[2*i+1]) * RS2;
        }
    }
}

template<int N>
__device__ __forceinline__ void idwt_pass(float* T, int tid, int sLine, int sA, int sB, int nA, int nB) {
    const int nl = nA * nB;
    for (int li = tid; li < nl; li += NTHREADS) {
        int a = li / nB, b = li - a * nB;
        float* p = T + a * sA + b * sB;
        float v[N];
#pragma unroll
        for (int k = 0; k < N; k++) v[k] = p[k * sLine];
#pragma unroll
        for (int i = 0; i < N / 2; i++) {
            p[(2*i)   * sLine] = (v[i] + v[i + N/2]) * RS2;
            p[(2*i+1) * sLine] = (v[i] - v[i + N/2]) * RS2;
        }
    }
}

// ---- one 8x8 slice of one block for one normal: fwd pyramid + threshold + inv, accumulate/3 ----
__device__ __forceinline__ void bandlet_slice(const float* T, float* A,
        int bd, int bh, int bw, int n, int s, int abase) {
    int soff, si, sj, aoff, ai, aj;
    if (n == 0)      { soff = (bd+s)*SD + bh*SH + bw;     si = SH; sj = 1;  aoff = s*64; ai = 8;  aj = 1; }
    else if (n == 1) { soff = bd*SD + (bh+s)*SH + bw;     si = SD; sj = 1;  aoff = s*8;  ai = 64; aj = 1; }
    else             { soff = bd*SD + bh*SH + (bw+s);     si = SD; sj = SH; aoff = s;    ai = 64; aj = 8; }

    float v[64];
#pragma unroll
    for (int i = 0; i < 8; i++)
#pragma unroll
        for (int j = 0; j < 8; j++)
            v[i*8+j] = T[soff + i*si + j*sj];

    // forward 2D Haar pyramid: levels 8,4,2 ; rows then cols (matches reference)
#pragma unroll
    for (int lev = 0; lev < 3; lev++) {
        const int S = 8 >> lev, H = S >> 1;
#pragma unroll
        for (int j = 0; j < S; j++) {
            float t[4], u[4];
#pragma unroll
            for (int i = 0; i < H; i++) {
                float a = v[(2*i)*8+j], b = v[(2*i+1)*8+j];
                t[i] = (a + b) * RS2; u[i] = (a - b) * RS2;
            }
#pragma unroll
            for (int i = 0; i < H; i++) { v[i*8+j] = t[i]; v[(i+H)*8+j] = u[i]; }
        }
#pragma unroll
        for (int i = 0; i < S; i++) {
            float t[4], u[4];
#pragma unroll
            for (int j = 0; j < H; j++) {
                float a = v[i*8+2*j], b = v[i*8+2*j+1];
                t[j] = (a + b) * RS2; u[j] = (a - b) * RS2;
            }
#pragma unroll
            for (int j = 0; j < H; j++) { v[i*8+j] = t[j]; v[i*8+j+H] = u[j]; }
        }
    }

    // soft threshold, keep DC at [0,0]
#pragma unroll
    for (int e = 1; e < 64; e++)
        v[e] = copysignf(fmaxf(fabsf(v[e]) - TAU_V, 0.0f), v[e]);

    // inverse pyramid: levels 2,4,8 ; cols then rows (matches reference)
#pragma unroll
    for (int lev = 2; lev >= 0; lev--) {
        const int S = 8 >> lev, H = S >> 1;
#pragma unroll
        for (int i = 0; i < S; i++) {
            float t[4], u[4];
#pragma unroll
            for (int j = 0; j < H; j++) {
                float lo = v[i*8+j], hi = v[i*8+j+H];
                t[j] = (lo + hi) * RS2; u[j] = (lo - hi) * RS2;
            }
#pragma unroll
            for (int j = 0; j < H; j++) { v[i*8+2*j] = t[j]; v[i*8+2*j+1] = u[j]; }
        }
#pragma unroll
        for (int j = 0; j < S; j++) {
            float t[4], u[4];
#pragma unroll
            for (int i = 0; i < H; i++) {
                float lo = v[i*8+j], hi = v[(i+H)*8+j];
                t[i] = (lo + hi) * RS2; u[i] = (lo - hi) * RS2;
            }
#pragma unroll
            for (int i = 0; i < H; i++) { v[(2*i)*8+j] = t[i]; v[(2*i+1)*8+j] = u[i]; }
        }
    }

#pragma unroll
    for (int i = 0; i < 8; i++)
#pragma unroll
        for (int j = 0; j < 8; j++)
            atomicAdd(&A[abase + aoff + i*ai + j*aj], v[i*8+j] * (1.0f / 3.0f));
}

__global__ __launch_bounds__(NTHREADS, 1)
void bandlet3d_kernel(const float* __restrict__ x, float* __restrict__ y) {
    float* T = smem;           // 32^3 tile, strides (SD, SH, 1)
    float* A = smem + TILE_F;  // accumulator for up to 32 blocks
    const int tid = threadIdx.x;

    const int bc = blockIdx.x;
    const int batch = bc / 125;
    const int rem = bc - batch * 125;
    const int td = rem / 25;
    const int th = (rem / 5) % 5;
    const int tw = rem % 5;
    const long long gbase = (long long)batch * 4096000LL
                          + (long long)td * 32 * 25600 + th * 32 * 160 + tw * 32;

    // load tile (coalesced: 32 consecutive floats per warp-row)
    for (int l = tid; l < 32768; l += NTHREADS) {
        int w = l & 31, h = (l >> 5) & 31, d = l >> 10;
        T[d*SD + h*SH + w] = x[gbase + d*25600 + h*160 + w];
    }
    for (int l = tid; l < ACC_F; l += NTHREADS) A[l] = 0.0f;
    __syncthreads();

    // ---- forward 3D DWT level 1 (in place; lo->[0:16), hi->[16:32) per axis) ----
    dwt_pass<32>(T, tid, 1,  SD, SH, 32, 32); __syncthreads(); // w
    dwt_pass<32>(T, tid, SH, SD, 1,  32, 32); __syncthreads(); // h
    dwt_pass<32>(T, tid, SD, SH, 1,  32, 32); __syncthreads(); // d

    // ---- level-1 bandlet blocks: 56 detail blocks out of 64 slots, 2 batches of 32 ----
    for (int b0 = 0; b0 < 64; b0 += 32) {
        for (int t = tid; t < 32 * 24; t += NTHREADS) {
            int bib = t / 24;
            int rr  = t - bib * 24;
            int slot = b0 + bib;
            int d3 = (slot >> 4) & 3, h3 = (slot >> 2) & 3, w3 = slot & 3;
            if (d3 < 2 && h3 < 2 && w3 < 2) continue;   // lll octant: not processed here
            bandlet_slice(T, A, d3*8, h3*8, w3*8, rr >> 3, rr & 7, bib * 512);
        }
        __syncthreads();
        for (int e = tid; e < 32 * 512; e += NTHREADS) {
            int bib = e >> 9, off = e & 511;
            int slot = b0 + bib;
            int d3 = (slot >> 4) & 3, h3 = (slot >> 2) & 3, w3 = slot & 3;
            if (!(d3 < 2 && h3 < 2 && w3 < 2)) {
                int ld = off >> 6, lh = (off >> 3) & 7, lw = off & 7;
                T[(d3*8+ld)*SD + (h3*8+lh)*SH + (w3*8+lw)] = A[e];
            }
            A[e] = 0.0f;   // reset for next use
        }
        __syncthreads();
    }

    // ---- forward 3D DWT level 2 on lll corner [0:16)^3 ----
    dwt_pass<16>(T, tid, 1,  SD, SH, 16, 16); __syncthreads();
    dwt_pass<16>(T, tid, SH, SD, 1,  16, 16); __syncthreads();
    dwt_pass<16>(T, tid, SD, SH, 1,  16, 16); __syncthreads();

    // ---- level-2 bandlet blocks: 7 detail blocks (slot 0 = lll2 preserved) ----
    for (int t = tid; t < 8 * 24; t += NTHREADS) {
        int slot = t / 24;
        if (slot == 0) continue;
        int rr = t - slot * 24;
        int d3 = (slot >> 2) & 1, h3 = (slot >> 1) & 1, w3 = slot & 1;
        bandlet_slice(T, A, d3*8, h3*8, w3*8, rr >> 3, rr & 7, slot * 512);
    }
    __syncthreads();
    for (int e = tid; e < 8 * 512; e += NTHREADS) {
        int slot = e >> 9, off = e & 511;
        if (slot != 0) {
            int d3 = (slot >> 2) & 1, h3 = (slot >> 1) & 1, w3 = slot & 1;
            int ld = off >> 6, lh = (off >> 3) & 7, lw = off & 7;
            T[(d3*8+ld)*SD + (h3*8+lh)*SH + (w3*8+lw)] = A[e];
        }
    }
    __syncthreads();

    // ---- inverse DWT level 2 ----
    idwt_pass<16>(T, tid, 1,  SD, SH, 16, 16); __syncthreads();
    idwt_pass<16>(T, tid, SH, SD, 1,  16, 16); __syncthreads();
    idwt_pass<16>(T, tid, SD, SH, 1,  16, 16); __syncthreads();

    // ---- inverse DWT level 1 ----
    idwt_pass<32>(T, tid, 1,  SD, SH, 32, 32); __syncthreads();
    idwt_pass<32>(T, tid, SH, SD, 1,  32, 32); __syncthreads();
    idwt_pass<32>(T, tid, SD, SH, 1,  32, 32); __syncthreads();

    // store tile
    for (int l = tid; l < 32768; l += NTHREADS) {
        int w = l & 31, h = (l >> 5) & 31, d = l >> 10;
        y[gbase + d*25600 + h*160 + w] = T[d*SD + h*SH + w];
    }
}

extern "C" void kernel_launch(void* const* d_in, const int* in_sizes, int n_in,
                              void* d_out, int out_size) {
    const float* x = (const float*)d_in[0];
    float* y = (float*)d_out;
    (void)in_sizes; (void)n_in; (void)out_size;

    const size_t smem_bytes = (size_t)(TILE_F + ACC_F) * sizeof(float); // 204928 B
    cudaFuncSetAttribute(bandlet3d_kernel,
                         cudaFuncAttributeMaxDynamicSharedMemorySize, (int)smem_bytes);
    bandlet3d_kernel<<<250, NTHREADS, smem_bytes>>>(x, y);
}

// round 2
// speedup vs baseline: 1.1030x; 1.1030x over previous
#include <cuda_runtime.h>

#define RS2 0.7071067811865476f
#define TAU_V 0.05f

constexpr int SH = 33;
constexpr int SD = 33 * 33;          // 1089
constexpr int TILE_F = 32 * SD;      // 34848 floats
constexpr int ACC_F  = 32 * 512;     // 16384 floats
constexpr int NTHREADS = 512;

extern __shared__ float smem[];

// ---- one axis pass of length-N Haar DWT over a family of lines (in place) ----
template<int N>
__device__ __forceinline__ void dwt_pass(float* T, int tid, int sLine, int sA, int sB, int nA, int nB) {
    const int nl = nA * nB;
    for (int li = tid; li < nl; li += NTHREADS) {
        int a = li / nB, b = li - a * nB;
        float* p = T + a * sA + b * sB;
        float v[N];
#pragma unroll
        for (int k = 0; k < N; k++) v[k] = p[k * sLine];
#pragma unroll
        for (int i = 0; i < N / 2; i++) {
            p[i * sLine]         = (v[2*i] + v[2*i+1]) * RS2;
            p[(i + N/2) * sLine] = (v[2*i] - v[2*i+1]) * RS2;
        }
    }
}

template<int N>
__device__ __forceinline__ void idwt_pass(float* T, int tid, int sLine, int sA, int sB, int nA, int nB) {
    const int nl = nA * nB;
    for (int li = tid; li < nl; li += NTHREADS) {
        int a = li / nB, b = li - a * nB;
        float* p = T + a * sA + b * sB;
        float v[N];
#pragma unroll
        for (int k = 0; k < N; k++) v[k] = p[k * sLine];
#pragma unroll
        for (int i = 0; i < N / 2; i++) {
            p[(2*i)   * sLine] = (v[i] + v[i + N/2]) * RS2;
            p[(2*i+1) * sLine] = (v[i] - v[i + N/2]) * RS2;
        }
    }
}

// ---- one 8x8 slice of one block for one normal: fwd pyramid + threshold + inv, accumulate ----
__device__ __forceinline__ void bandlet_slice(const float* T, float* A,
        int bd, int bh, int bw, int n, int s, int abase) {
    int soff, si, sj, aoff, ai, aj;
    if (n == 0)      { soff = (bd+s)*SD + bh*SH + bw;     si = SH; sj = 1;  aoff = s*64; ai = 8;  aj = 1; }
    else if (n == 1) { soff = bd*SD + (bh+s)*SH + bw;     si = SD; sj = 1;  aoff = s*8;  ai = 64; aj = 1; }
    else             { soff = bd*SD + bh*SH + (bw+s);     si = SD; sj = SH; aoff = s;    ai = 64; aj = 8; }

    float v[64];
#pragma unroll
    for (int i = 0; i < 8; i++)
#pragma unroll
        for (int j = 0; j < 8; j++)
            v[i*8+j] = T[soff + i*si + j*sj];

    // forward 2D Haar pyramid: levels 8,4,2 ; rows then cols (matches reference)
#pragma unroll
    for (int lev = 0; lev < 3; lev++) {
        const int S = 8 >> lev, H = S >> 1;
#pragma unroll
        for (int j = 0; j < S; j++) {
            float t[4], u[4];
#pragma unroll
            for (int i = 0; i < H; i++) {
                float a = v[(2*i)*8+j], b = v[(2*i+1)*8+j];
                t[i] = (a + b) * RS2; u[i] = (a - b) * RS2;
            }
#pragma unroll
            for (int i = 0; i < H; i++) { v[i*8+j] = t[i]; v[(i+H)*8+j] = u[i]; }
        }
#pragma unroll
        for (int i = 0; i < S; i++) {
            float t[4], u[4];
#pragma unroll
            for (int j = 0; j < H; j++) {
                float a = v[i*8+2*j], b = v[i*8+2*j+1];
                t[j] = (a + b) * RS2; u[j] = (a - b) * RS2;
            }
#pragma unroll
            for (int j = 0; j < H; j++) { v[i*8+j] = t[j]; v[i*8+j+H] = u[j]; }
        }
    }

    // soft threshold, keep DC at [0,0]
#pragma unroll
    for (int e = 1; e < 64; e++)
        v[e] = copysignf(fmaxf(fabsf(v[e]) - TAU_V, 0.0f), v[e]);

    // inverse pyramid: levels 2,4,8 ; cols then rows (matches reference)
#pragma unroll
    for (int lev = 2; lev >= 0; lev--) {
        const int S = 8 >> lev, H = S >> 1;
#pragma unroll
        for (int i = 0; i < S; i++) {
            float t[4], u[4];
#pragma unroll
            for (int j = 0; j < H; j++) {
                float lo = v[i*8+j], hi = v[i*8+j+H];
                t[j] = (lo + hi) * RS2; u[j] = (lo - hi) * RS2;
            }
#pragma unroll
            for (int j = 0; j < H; j++) { v[i*8+2*j] = t[j]; v[i*8+2*j+1] = u[j]; }
        }
#pragma unroll
        for (int j = 0; j < S; j++) {
            float t[4], u[4];
#pragma unroll
            for (int i = 0; i < H; i++) {
                float lo = v[i*8+j], hi = v[(i+H)*8+j];
                t[i] = (lo + hi) * RS2; u[i] = (lo - hi) * RS2;
            }
#pragma unroll
            for (int i = 0; i < H; i++) { v[(2*i)*8+j] = t[i]; v[(2*i+1)*8+j] = u[i]; }
        }
    }

    // raw accumulate; the /3 is applied once at writeback
#pragma unroll
    for (int i = 0; i < 8; i++)
#pragma unroll
        for (int j = 0; j < 8; j++)
            atomicAdd(&A[abase + aoff + i*ai + j*aj], v[i*8+j]);
}

__global__ __launch_bounds__(NTHREADS, 1)
void bandlet3d_kernel(const float* __restrict__ x, float* __restrict__ y) {
    float* T = smem;           // 32^3 tile, strides (SD, SH, 1)
    float* A = smem + TILE_F;  // accumulator for up to 32 blocks
    const int tid = threadIdx.x;

    const int bc = blockIdx.x;
    const int batch = bc / 125;
    const int rem = bc - batch * 125;
    const int td = rem / 25;
    const int th = (rem / 5) % 5;
    const int tw = rem % 5;
    const long long gbase = (long long)batch * 4096000LL
                          + (long long)td * 32 * 25600 + th * 32 * 160 + tw * 32;

    // load tile (coalesced: 32 consecutive floats per warp-row)
    for (int l = tid; l < 32768; l += NTHREADS) {
        int w = l & 31, h = (l >> 5) & 31, d = l >> 10;
        T[d*SD + h*SH + w] = x[gbase + d*25600 + h*160 + w];
    }
    for (int l = tid; l < ACC_F; l += NTHREADS) A[l] = 0.0f;
    __syncthreads();

    // ---- forward 3D DWT level 1 (in place; lo->[0:16), hi->[16:32) per axis) ----
    dwt_pass<32>(T, tid, 1,  SD, SH, 32, 32); __syncthreads(); // w
    dwt_pass<32>(T, tid, SH, SD, 1,  32, 32); __syncthreads(); // h
    dwt_pass<32>(T, tid, SD, SH, 1,  32, 32); __syncthreads(); // d

    // ---- level-1 bandlet blocks: 56 detail blocks out of 64 slots, 2 batches of 32 ----
    for (int b0 = 0; b0 < 64; b0 += 32) {
        for (int t = tid; t < 32 * 24; t += NTHREADS) {
            int bib = t / 24;
            int rr  = t - bib * 24;
            int slot = b0 + bib;
            int d3 = (slot >> 4) & 3, h3 = (slot >> 2) & 3, w3 = slot & 3;
            if (d3 < 2 && h3 < 2 && w3 < 2) continue;   // lll octant: not processed here
            bandlet_slice(T, A, d3*8, h3*8, w3*8, rr >> 3, rr & 7, bib * 512);
        }
        __syncthreads();
        for (int e = tid; e < 32 * 512; e += NTHREADS) {
            int bib = e >> 9, off = e & 511;
            int slot = b0 + bib;
            int d3 = (slot >> 4) & 3, h3 = (slot >> 2) & 3, w3 = slot & 3;
            if (!(d3 < 2 && h3 < 2 && w3 < 2)) {
                int ld = off >> 6, lh = (off >> 3) & 7, lw = off & 7;
                T[(d3*8+ld)*SD + (h3*8+lh)*SH + (w3*8+lw)] = A[e] * (1.0f / 3.0f);
            }
            A[e] = 0.0f;   // reset for next use
        }
        __syncthreads();
    }

    // ---- forward 3D DWT level 2 on lll corner [0:16)^3 ----
    dwt_pass<16>(T, tid, 1,  SD, SH, 16, 16); __syncthreads();
    dwt_pass<16>(T, tid, SH, SD, 1,  16, 16); __syncthreads();
    dwt_pass<16>(T, tid, SD, SH, 1,  16, 16); __syncthreads();

    // ---- level-2 bandlet blocks: 7 detail blocks (slot 0 = lll2 preserved) ----
    for (int t = tid; t < 8 * 24; t += NTHREADS) {
        int slot = t / 24;
        if (slot == 0) continue;
        int rr = t - slot * 24;
        int d3 = (slot >> 2) & 1, h3 = (slot >> 1) & 1, w3 = slot & 1;
        bandlet_slice(T, A, d3*8, h3*8, w3*8, rr >> 3, rr & 7, slot * 512);
    }
    __syncthreads();
    for (int e = tid; e < 8 * 512; e += NTHREADS) {
        int slot = e >> 9, off = e & 511;
        if (slot != 0) {
            int d3 = (slot >> 2) & 1, h3 = (slot >> 1) & 1, w3 = slot & 1;
            int ld = off >> 6, lh = (off >> 3) & 7, lw = off & 7;
            T[(d3*8+ld)*SD + (h3*8+lh)*SH + (w3*8+lw)] = A[e] * (1.0f / 3.0f);
        }
    }
    __syncthreads();

    // ---- inverse DWT level 2 ----
    idwt_pass<16>(T, tid, 1,  SD, SH, 16, 16); __syncthreads();
    idwt_pass<16>(T, tid, SH, SD, 1,  16, 16); __syncthreads();
    idwt_pass<16>(T, tid, SD, SH, 1,  16, 16); __syncthreads();

    // ---- inverse DWT level 1 ----
    idwt_pass<32>(T, tid, 1,  SD, SH, 32, 32); __syncthreads();
    idwt_pass<32>(T, tid, SH, SD, 1,  32, 32); __syncthreads();
    idwt_pass<32>(T, tid, SD, SH, 1,  32, 32); __syncthreads();

    // store tile
    for (int l = tid; l < 32768; l += NTHREADS) {
        int w = l & 31, h = (l >> 5) & 31, d = l >> 10;
        y[gbase + d*25600 + h*160 + w] = T[d*SD + h*SH + w];
    }
}

extern "C" void kernel_launch(void* const* d_in, const int* in_sizes, int n_in,
                              void* d_out, int out_size) {
    const float* x = (const float*)d_in[0];
    float* y = (float*)d_out;
    (void)in_sizes; (void)n_in; (void)out_size;

    const size_t smem_bytes = (size_t)(TILE_F + ACC_F) * sizeof(float); // 204928 B
    cudaFuncSetAttribute(bandlet3d_kernel,
                         cudaFuncAttributeMaxDynamicSharedMemorySize, (int)smem_bytes);
    bandlet3d_kernel<<<250, NTHREADS, smem_bytes>>>(x, y);
}

// round 3
// speedup vs baseline: 2.5857x; 2.3442x over previous
#include <cuda_runtime.h>

#define RS2 0.7071067811865476f
#define TAU_V 0.05f

constexpr int SH = 33;
constexpr int SD = 33 * 33;          // 1089  (≡1 mod 32 → conflict-free line access)
constexpr int TILE_F = 32 * SD;      // 34848 floats
// accumulator: logical (a,b,c) -> 73a + 9b + c ; block stride 584
constexpr int ABLK = 584;
constexpr int ACC_F = 32 * ABLK;     // 18688 floats
constexpr int NTHREADS = 512;

extern __shared__ float smem[];

template<int N>
__device__ __forceinline__ void dwt_pass(float* T, int tid, int sLine, int sA, int sB, int nA, int nB) {
    const int nl = nA * nB;
    for (int li = tid; li < nl; li += NTHREADS) {
        int a = li / nB, b = li - a * nB;
        float* p = T + a * sA + b * sB;
        float v[N];
#pragma unroll
        for (int k = 0; k < N; k++) v[k] = p[k * sLine];
#pragma unroll
        for (int i = 0; i < N / 2; i++) {
            p[i * sLine]         = (v[2*i] + v[2*i+1]) * RS2;
            p[(i + N/2) * sLine] = (v[2*i] - v[2*i+1]) * RS2;
        }
    }
}

template<int N>
__device__ __forceinline__ void idwt_pass(float* T, int tid, int sLine, int sA, int sB, int nA, int nB) {
    const int nl = nA * nB;
    for (int li = tid; li < nl; li += NTHREADS) {
        int a = li / nB, b = li - a * nB;
        float* p = T + a * sA + b * sB;
        float v[N];
#pragma unroll
        for (int k = 0; k < N; k++) v[k] = p[k * sLine];
#pragma unroll
        for (int i = 0; i < N / 2; i++) {
            p[(2*i)   * sLine] = (v[i] + v[i + N/2]) * RS2;
            p[(2*i+1) * sLine] = (v[i] - v[i + N/2]) * RS2;
        }
    }
}

// load slice (normal n, slice s) of block at (bd,bh,bw) from T; fwd pyramid; threshold; inv pyramid.
// result left in v[64] (row-major i*8+j of the slice's own 2D frame).
__device__ __forceinline__ void bandlet_compute(const float* T, float* v,
        int bd, int bh, int bw, int n, int s) {
    int soff, si, sj;
    if (n == 0)      { soff = (bd+s)*SD + bh*SH + bw;     si = SH; sj = 1;  }
    else if (n == 1) { soff = bd*SD + (bh+s)*SH + bw;     si = SD; sj = 1;  }
    else             { soff = bd*SD + bh*SH + (bw+s);     si = SD; sj = SH; }

#pragma unroll
    for (int i = 0; i < 8; i++)
#pragma unroll
        for (int j = 0; j < 8; j++)
            v[i*8+j] = T[soff + i*si + j*sj];

    // forward 2D Haar pyramid: levels 8,4,2 ; rows then cols
#pragma unroll
    for (int lev = 0; lev < 3; lev++) {
        const int S = 8 >> lev, H = S >> 1;
#pragma unroll
        for (int j = 0; j < S; j++) {
            float t[4], u[4];
#pragma unroll
            for (int i = 0; i < H; i++) {
                float a = v[(2*i)*8+j], b = v[(2*i+1)*8+j];
                t[i] = (a + b) * RS2; u[i] = (a - b) * RS2;
            }
#pragma unroll
            for (int i = 0; i < H; i++) { v[i*8+j] = t[i]; v[(i+H)*8+j] = u[i]; }
        }
#pragma unroll
        for (int i = 0; i < S; i++) {
            float t[4], u[4];
#pragma unroll
            for (int j = 0; j < H; j++) {
                float a = v[i*8+2*j], b = v[i*8+2*j+1];
                t[j] = (a + b) * RS2; u[j] = (a - b) * RS2;
            }
#pragma unroll
            for (int j = 0; j < H; j++) { v[i*8+j] = t[j]; v[i*8+j+H] = u[j]; }
        }
    }

    // soft threshold, keep DC
#pragma unroll
    for (int e = 1; e < 64; e++)
        v[e] = copysignf(fmaxf(fabsf(v[e]) - TAU_V, 0.0f), v[e]);

    // inverse pyramid: levels 2,4,8 ; cols then rows
#pragma unroll
    for (int lev = 2; lev >= 0; lev--) {
        const int S = 8 >> lev, H = S >> 1;
#pragma unroll
        for (int i = 0; i < S; i++) {
            float t[4], u[4];
#pragma unroll
            for (int j = 0; j < H; j++) {
                float lo = v[i*8+j], hi = v[i*8+j+H];
                t[j] = (lo + hi) * RS2; u[j] = (lo - hi) * RS2;
            }
#pragma unroll
            for (int j = 0; j < H; j++) { v[i*8+2*j] = t[j]; v[i*8+2*j+1] = u[j]; }
        }
#pragma unroll
        for (int j = 0; j < S; j++) {
            float t[4], u[4];
#pragma unroll
            for (int i = 0; i < H; i++) {
                float lo = v[i*8+j], hi = v[(i+H)*8+j];
                t[i] = (lo + hi) * RS2; u[i] = (lo - hi) * RS2;
            }
#pragma unroll
            for (int i = 0; i < H; i++) { v[(2*i)*8+j] = t[i]; v[(2*i+1)*8+j] = u[i]; }
        }
    }
}

// Process nblk blocks (8 slots each described by decode fn) in 3 normal-phases.
// decode: slot index -> (d3,h3,w3) multipliers (block origin /8), or inactive.
template<bool LEVEL1>
__device__ __forceinline__ void bandlet_blocks(float* T, float* A, int tid, int b0) {
    const int t = tid;
    const int bib = t >> 3;          // block-in-batch 0..31 (or 0..7 for level 2)
    const int s   = t & 7;
    int bd = 0, bh = 0, bw = 0;
    bool active = false;
    if (LEVEL1) {
        if (t < 32 * 8) {
            int slot = b0 + bib;
            int d3 = (slot >> 4) & 3, h3 = (slot >> 2) & 3, w3 = slot & 3;
            active = !(d3 < 2 && h3 < 2 && w3 < 2);
            bd = d3 * 8; bh = h3 * 8; bw = w3 * 8;
        }
    } else {
        if (t < 8 * 8) {
            int slot = bib;
            active = (slot != 0);
            int d3 = (slot >> 2) & 1, h3 = (slot >> 1) & 1, w3 = slot & 1;
            bd = d3 * 8; bh = h3 * 8; bw = w3 * 8;
        }
    }
    const int abase = bib * ABLK;
    float v[64];

    // phase 0: normal 0 -> plain store   (a,b,c)=(s,i,j) -> 73s + 9i + j
    if (active) {
        bandlet_compute(T, v, bd, bh, bw, 0, s);
#pragma unroll
        for (int i = 0; i < 8; i++)
#pragma unroll
            for (int j = 0; j < 8; j++)
                A[abase + 73*s + 9*i + j] = v[i*8+j];
    }
    __syncthreads();

    // phase 1: normal 1 -> add           (a,b,c)=(i,s,j) -> 73i + 9s + j
    if (active) {
        bandlet_compute(T, v, bd, bh, bw, 1, s);
#pragma unroll
        for (int i = 0; i < 8; i++)
#pragma unroll
            for (int j = 0; j < 8; j++)
                A[abase + 73*i + 9*s + j] += v[i*8+j];
    }
    __syncthreads();

    // phase 2: normal 2 -> sum + write back into T  (a,b,c)=(i,j,s) -> 73i + 9j + s
    if (active) {
        bandlet_compute(T, v, bd, bh, bw, 2, s);
#pragma unroll
        for (int i = 0; i < 8; i++)
#pragma unroll
            for (int j = 0; j < 8; j++)
                v[i*8+j] = (v[i*8+j] + A[abase + 73*i + 9*j + s]) * (1.0f / 3.0f);
    }
    __syncthreads();   // all T reads (this phase) done before T writes
    if (active) {
#pragma unroll
        for (int i = 0; i < 8; i++)
#pragma unroll
            for (int j = 0; j < 8; j++)
                T[(bd+i)*SD + (bh+j)*SH + (bw+s)] = v[i*8+j];
    }
    __syncthreads();
}

__global__ __launch_bounds__(NTHREADS, 1)
void bandlet3d_kernel(const float* __restrict__ x, float* __restrict__ y) {
    float* T = smem;           // 32^3 tile, strides (SD, SH, 1)
    float* A = smem + TILE_F;  // conflict-free accumulator, 32 blocks
    const int tid = threadIdx.x;

    const int bc = blockIdx.x;
    const int batch = bc / 125;
    const int rem = bc - batch * 125;
    const int td = rem / 25;
    const int th = (rem / 5) % 5;
    const int tw = rem % 5;
    const long long gbase = (long long)batch * 4096000LL
                          + (long long)td * 32 * 25600 + th * 32 * 160 + tw * 32;

    for (int l = tid; l < 32768; l += NTHREADS) {
        int w = l & 31, h = (l >> 5) & 31, d = l >> 10;
        T[d*SD + h*SH + w] = x[gbase + d*25600 + h*160 + w];
    }
    __syncthreads();

    // forward 3D DWT level 1
    dwt_pass<32>(T, tid, 1,  SD, SH, 32, 32); __syncthreads();
    dwt_pass<32>(T, tid, SH, SD, 1,  32, 32); __syncthreads();
    dwt_pass<32>(T, tid, SD, SH, 1,  32, 32); __syncthreads();

    // level-1 bandlet: 56 detail blocks in 2 batches of 32 slots
    bandlet_blocks<true>(T, A, tid, 0);
    bandlet_blocks<true>(T, A, tid, 32);

    // forward 3D DWT level 2 on [0:16)^3
    dwt_pass<16>(T, tid, 1,  SD, SH, 16, 16); __syncthreads();
    dwt_pass<16>(T, tid, SH, SD, 1,  16, 16); __syncthreads();
    dwt_pass<16>(T, tid, SD, SH, 1,  16, 16); __syncthreads();

    // level-2 bandlet: 7 detail blocks
    bandlet_blocks<false>(T, A, tid, 0);

    // inverse DWT level 2
    idwt_pass<16>(T, tid, 1,  SD, SH, 16, 16); __syncthreads();
    idwt_pass<16>(T, tid, SH, SD, 1,  16, 16); __syncthreads();
    idwt_pass<16>(T, tid, SD, SH, 1,  16, 16); __syncthreads();

    // inverse DWT level 1
    idwt_pass<32>(T, tid, 1,  SD, SH, 32, 32); __syncthreads();
    idwt_pass<32>(T, tid, SH, SD, 1,  32, 32); __syncthreads();
    idwt_pass<32>(T, tid, SD, SH, 1,  32, 32); __syncthreads();

    for (int l = tid; l < 32768; l += NTHREADS) {
        int w = l & 31, h = (l >> 5) & 31, d = l >> 10;
        y[gbase + d*25600 + h*160 + w] = T[d*SD + h*SH + w];
    }
}

extern "C" void kernel_launch(void* const* d_in, const int* in_sizes, int n_in,
                              void* d_out, int out_size) {
    const float* x = (const float*)d_in[0];
    float* y = (float*)d_out;
    (void)in_sizes; (void)n_in; (void)out_size;

    const size_t smem_bytes = (size_t)(TILE_F + ACC_F) * sizeof(float); // 214144 B
    cudaFuncSetAttribute(bandlet3d_kernel,
                         cudaFuncAttributeMaxDynamicSharedMemorySize, (int)smem_bytes);
    bandlet3d_kernel<<<250, NTHREADS, smem_bytes>>>(x, y);
}

// round 4
// speedup vs baseline: 3.8162x; 1.4759x over previous
#include <cuda_runtime.h>

#define RS2 0.7071067811865476f
#define TAU_V 0.05f

constexpr int SH = 33;
constexpr int SD = 33 * 33;          // 1089  (≡1 mod 32 → conflict-free strided access)
constexpr int TILE_F = 32 * SD;      // 34848 floats = 139392 B
constexpr int NTHREADS = 512;

// valid level-1 band-block slots (slot = d3*16 + h3*4 + w3, excluding lll octant)
__device__ __constant__ unsigned char VSLOT[56] = {
    2,3,6,7,8,9,10,11,12,13,14,15,18,19,22,23,
    24,25,26,27,28,29,30,31,32,33,34,35,36,37,38,39,
    40,41,42,43,44,45,46,47,48,49,50,51,52,53,54,55,
    56,57,58,59,60,61,62,63
};

extern __shared__ float smem[];

template<int N>
__device__ __forceinline__ void dwt_pass(float* T, int tid, int sLine, int sA, int sB, int nA, int nB) {
    const int nl = nA * nB;
    for (int li = tid; li < nl; li += NTHREADS) {
        int a = li / nB, b = li - a * nB;
        float* p = T + a * sA + b * sB;
        float v[N];
#pragma unroll
        for (int k = 0; k < N; k++) v[k] = p[k * sLine];
#pragma unroll
        for (int i = 0; i < N / 2; i++) {
            p[i * sLine]         = (v[2*i] + v[2*i+1]) * RS2;
            p[(i + N/2) * sLine] = (v[2*i] - v[2*i+1]) * RS2;
        }
    }
}

template<int N>
__device__ __forceinline__ void idwt_pass(float* T, int tid, int sLine, int sA, int sB, int nA, int nB) {
    const int nl = nA * nB;
    for (int li = tid; li < nl; li += NTHREADS) {
        int a = li / nB, b = li - a * nB;
        float* p = T + a * sA + b * sB;
        float v[N];
#pragma unroll
        for (int k = 0; k < N; k++) v[k] = p[k * sLine];
#pragma unroll
        for (int i = 0; i < N / 2; i++) {
            p[(2*i)   * sLine] = (v[i] + v[i + N/2]) * RS2;
            p[(2*i+1) * sLine] = (v[i] - v[i + N/2]) * RS2;
        }
    }
}

// load slice (normal n, slice s) of block at (bd,bh,bw); fwd pyramid; threshold; inv pyramid.
// result left in v[64] (row-major i*8+j of the slice's 2D frame).
__device__ __forceinline__ void bandlet_compute(const float* T, float* v,
        int bd, int bh, int bw, int n, int s) {
    int soff, si, sj;
    if (n == 0)      { soff = (bd+s)*SD + bh*SH + bw;     si = SH; sj = 1;  }
    else if (n == 1) { soff = bd*SD + (bh+s)*SH + bw;     si = SD; sj = 1;  }
    else             { soff = bd*SD + bh*SH + (bw+s);     si = SD; sj = SH; }

#pragma unroll
    for (int i = 0; i < 8; i++)
#pragma unroll
        for (int j = 0; j < 8; j++)
            v[i*8+j] = T[soff + i*si + j*sj];

    // forward 2D Haar pyramid: levels 8,4,2 ; rows then cols
#pragma unroll
    for (int lev = 0; lev < 3; lev++) {
        const int S = 8 >> lev, H = S >> 1;
#pragma unroll
        for (int j = 0; j < S; j++) {
            float t[4], u[4];
#pragma unroll
            for (int i = 0; i < H; i++) {
                float a = v[(2*i)*8+j], b = v[(2*i+1)*8+j];
                t[i] = (a + b) * RS2; u[i] = (a - b) * RS2;
            }
#pragma unroll
            for (int i = 0; i < H; i++) { v[i*8+j] = t[i]; v[(i+H)*8+j] = u[i]; }
        }
#pragma unroll
        for (int i = 0; i < S; i++) {
            float t[4], u[4];
#pragma unroll
            for (int j = 0; j < H; j++) {
                float a = v[i*8+2*j], b = v[i*8+2*j+1];
                t[j] = (a + b) * RS2; u[j] = (a - b) * RS2;
            }
#pragma unroll
            for (int j = 0; j < H; j++) { v[i*8+j] = t[j]; v[i*8+j+H] = u[j]; }
        }
    }

    // soft threshold, keep DC
#pragma unroll
    for (int e = 1; e < 64; e++)
        v[e] = copysignf(fmaxf(fabsf(v[e]) - TAU_V, 0.0f), v[e]);

    // inverse pyramid: levels 2,4,8 ; cols then rows
#pragma unroll
    for (int lev = 2; lev >= 0; lev--) {
        const int S = 8 >> lev, H = S >> 1;
#pragma unroll
        for (int i = 0; i < S; i++) {
            float t[4], u[4];
#pragma unroll
            for (int j = 0; j < H; j++) {
                float lo = v[i*8+j], hi = v[i*8+j+H];
                t[j] = (lo + hi) * RS2; u[j] = (lo - hi) * RS2;
            }
#pragma unroll
            for (int j = 0; j < H; j++) { v[i*8+2*j] = t[j]; v[i*8+2*j+1] = u[j]; }
        }
#pragma unroll
        for (int j = 0; j < S; j++) {
            float t[4], u[4];
#pragma unroll
            for (int i = 0; i < H; i++) {
                float lo = v[i*8+j], hi = v[(i+H)*8+j];
                t[i] = (lo + hi) * RS2; u[i] = (lo - hi) * RS2;
            }
#pragma unroll
            for (int i = 0; i < H; i++) { v[(2*i)*8+j] = t[i]; v[(2*i+1)*8+j] = u[i]; }
        }
    }
}

// writeback micro-phases: block regions are disjoint across groups, so only
// intra-group ordering (n0 -> n1 -> n2) needs barriers.
__device__ __forceinline__ void bandlet_group(float* T, int tid,
        int nrm, bool active, int bd, int bh, int bw, int s) {
    float v[64];
    if (active) bandlet_compute(T, v, bd, bh, bw, nrm, s);
    __syncthreads();
    if (active && nrm == 0) {
#pragma unroll
        for (int i = 0; i < 8; i++)
#pragma unroll
            for (int j = 0; j < 8; j++)
                T[(bd+s)*SD + (bh+i)*SH + (bw+j)] = v[i*8+j];
    }
    __syncthreads();
    if (active && nrm == 1) {
#pragma unroll
        for (int i = 0; i < 8; i++)
#pragma unroll
            for (int j = 0; j < 8; j++)
                T[(bd+i)*SD + (bh+s)*SH + (bw+j)] += v[i*8+j];
    }
    __syncthreads();
    if (active && nrm == 2) {
#pragma unroll
        for (int i = 0; i < 8; i++)
#pragma unroll
            for (int j = 0; j < 8; j++) {
                int idx = (bd+i)*SD + (bh+j)*SH + (bw+s);
                T[idx] = (T[idx] + v[i*8+j]) * (1.0f / 3.0f);
            }
    }
}

__global__ __launch_bounds__(NTHREADS, 1)
void bandlet3d_kernel(const float* __restrict__ x, float* __restrict__ y) {
    float* T = smem;           // 32^3 tile, strides (SD, SH, 1)
    const int tid = threadIdx.x;

    const int bc = blockIdx.x;
    const int batch = bc / 125;
    const int rem = bc - batch * 125;
    const int td = rem / 25;
    const int th = (rem / 5) % 5;
    const int tw = rem % 5;
    const long long gbase = (long long)batch * 4096000LL
                          + (long long)td * 32 * 25600 + th * 32 * 160 + tw * 32;

    // load tile: float4 global reads, scalar smem stores (odd strides)
    for (int l = tid; l < 8192; l += NTHREADS) {
        int w4 = l & 7, h = (l >> 3) & 31, d = l >> 8;
        float4 val = *reinterpret_cast<const float4*>(x + gbase + d*25600 + h*160 + w4*4);
        int t0 = d*SD + h*SH + w4*4;
        T[t0]   = val.x; T[t0+1] = val.y; T[t0+2] = val.z; T[t0+3] = val.w;
    }
    __syncthreads();

    // forward 3D DWT level 1
    dwt_pass<32>(T, tid, 1,  SD, SH, 32, 32); __syncthreads();
    dwt_pass<32>(T, tid, SH, SD, 1,  32, 32); __syncthreads();
    dwt_pass<32>(T, tid, SD, SH, 1,  32, 32); __syncthreads();

    // level-1 bandlet: 56 blocks in groups of 21/21/14; one thread per (block,normal,slice)
    for (int g = 0; g < 3; g++) {
        const int base = g * 21;
        const int nblk = (g == 2) ? 14 : 21;
        const int ntask = nblk * 8;          // per normal
        int nrm = 3, s = 0, bd = 0, bh = 0, bw = 0;
        bool active = (tid < 3 * ntask);
        if (active) {
            nrm = tid / ntask;
            int r = tid - nrm * ntask;
            int bg = r >> 3; s = r & 7;
            int slot = VSLOT[base + bg];
            bd = ((slot >> 4) & 3) * 8;
            bh = ((slot >> 2) & 3) * 8;
            bw = (slot & 3) * 8;
        }
        bandlet_group(T, tid, nrm, active, bd, bh, bw, s);
    }
    __syncthreads();

    // forward 3D DWT level 2 on [0:16)^3   (lll region — disjoint from bandlet writes)
    dwt_pass<16>(T, tid, 1,  SD, SH, 16, 16); __syncthreads();
    dwt_pass<16>(T, tid, SH, SD, 1,  16, 16); __syncthreads();
    dwt_pass<16>(T, tid, SD, SH, 1,  16, 16); __syncthreads();

    // level-2 bandlet: 7 blocks, one group, 168 parallel tasks
    {
        int nrm = 3, s = 0, bd = 0, bh = 0, bw = 0;
        bool active = (tid < 168);
        if (active) {
            nrm = tid / 56;
            int r = tid - nrm * 56;
            int bg = r >> 3; s = r & 7;
            int slot = bg + 1;
            bd = ((slot >> 2) & 1) * 8;
            bh = ((slot >> 1) & 1) * 8;
            bw = (slot & 1) * 8;
        }
        bandlet_group(T, tid, nrm, active, bd, bh, bw, s);
    }
    __syncthreads();

    // inverse DWT level 2
    idwt_pass<16>(T, tid, 1,  SD, SH, 16, 16); __syncthreads();
    idwt_pass<16>(T, tid, SH, SD, 1,  16, 16); __syncthreads();
    idwt_pass<16>(T, tid, SD, SH, 1,  16, 16); __syncthreads();

    // inverse DWT level 1
    idwt_pass<32>(T, tid, 1,  SD, SH, 32, 32); __syncthreads();
    idwt_pass<32>(T, tid, SH, SD, 1,  32, 32); __syncthreads();
    idwt_pass<32>(T, tid, SD, SH, 1,  32, 32); __syncthreads();

    // store tile: scalar smem loads, float4 global writes
    for (int l = tid; l < 8192; l += NTHREADS) {
        int w4 = l & 7, h = (l >> 3) & 31, d = l >> 8;
        int t0 = d*SD + h*SH + w4*4;
        float4 val = make_float4(T[t0], T[t0+1], T[t0+2], T[t0+3]);
        *reinterpret_cast<float4*>(y + gbase + d*25600 + h*160 + w4*4) = val;
    }
}

extern "C" void kernel_launch(void* const* d_in, const int* in_sizes, int n_in,
                              void* d_out, int out_size) {
    const float* x = (const float*)d_in[0];
    float* y = (float*)d_out;
    (void)in_sizes; (void)n_in; (void)out_size;

    const size_t smem_bytes = (size_t)TILE_F * sizeof(float); // 139392 B
    cudaFuncSetAttribute(bandlet3d_kernel,
                         cudaFuncAttributeMaxDynamicSharedMemorySize, (int)smem_bytes);
    bandlet3d_kernel<<<250, NTHREADS, smem_bytes>>>(x, y);
}